// round 2
// baseline (speedup 1.0000x reference)
#include <cuda_runtime.h>
#include <cstdint>

#define Nn 100000
#define Rr 8
#define Dd 64
#define Tt 16
#define Pp 32
#define Ee 1600000
#define KTOT (Rr*Dd + Dd)   // 576

// Scratch (device globals: no allocations allowed)
__device__ float g_S[(size_t)Nn*Rr*Dd];   // 204.8 MB per-(node,rel) message sums
__device__ float g_h[(size_t)Nn*Dd];      // layer-0 features
__device__ float g_h2[(size_t)Nn*Dd];     // layer-1 features
__device__ int   g_cnt[Nn*Rr];
__device__ float g_inv[Nn*Rr];

// ---------------------------------------------------------------------------
// 1. per-(dst, rel) edge counts
// ---------------------------------------------------------------------------
__global__ void count_k(const int* __restrict__ dst, const int* __restrict__ et) {
    int e = blockIdx.x*blockDim.x + threadIdx.x;
    if (e < Ee) atomicAdd(&g_cnt[dst[e]*Rr + et[e]], 1);
}

__global__ void inv_k() {
    int i = blockIdx.x*blockDim.x + threadIdx.x;
    if (i < Nn*Rr) g_inv[i] = 1.0f / (float)max(g_cnt[i], 1);
}

// ---------------------------------------------------------------------------
// 2. h0 = node_emb[x] + type_emb[node_type] + MLP(node_properties)
//    block = 256 threads = 4 nodes x 64 lanes; weights staged in SMEM
// ---------------------------------------------------------------------------
__global__ void mlp_k(const int* __restrict__ x, const int* __restrict__ ntype,
                      const float* __restrict__ props, const float* __restrict__ nemb,
                      const float* __restrict__ temb,
                      const float* __restrict__ w1, const float* __restrict__ b1,
                      const float* __restrict__ w2, const float* __restrict__ b2) {
    __shared__ float sw1[Pp*Dd];
    __shared__ float sw2[Dd*Dd];
    __shared__ float sb1[Dd], sb2[Dd];
    __shared__ float shid[4][Dd];
    for (int i = threadIdx.x; i < Pp*Dd; i += 256) sw1[i] = w1[i];
    for (int i = threadIdx.x; i < Dd*Dd; i += 256) sw2[i] = w2[i];
    if (threadIdx.x < Dd) { sb1[threadIdx.x] = b1[threadIdx.x]; sb2[threadIdx.x] = b2[threadIdx.x]; }
    __syncthreads();
    const int g = threadIdx.x >> 6, j = threadIdx.x & 63;
    for (int n0 = blockIdx.x*4; n0 < Nn; n0 += gridDim.x*4) {
        int n = n0 + g;
        float hj = 0.f;
        if (n < Nn) {
            hj = sb1[j];
            const float* pr = props + (size_t)n*Pp;
            #pragma unroll
            for (int p = 0; p < Pp; p++) hj = fmaf(__ldg(pr+p), sw1[p*Dd+j], hj);
            hj = fmaxf(hj, 0.f);
        }
        shid[g][j] = hj;
        __syncthreads();
        if (n < Nn) {
            float o = sb2[j];
            #pragma unroll
            for (int k = 0; k < Dd; k++) o = fmaf(shid[g][k], sw2[k*Dd+j], o);
            o += nemb[(size_t)x[n]*Dd + j] + temb[(size_t)ntype[n]*Dd + j];
            g_h[(size_t)n*Dd + j] = o;
        }
        __syncthreads();
    }
}

// ---------------------------------------------------------------------------
// 3. scatter: S[dst, et, :] += h[src, :]  (16 threads/edge, v4 reductions)
//    h is 25.6 MB -> L2-resident, so gathers are cheap; one random RMW pass.
// ---------------------------------------------------------------------------
__global__ void scatter_k(const float* __restrict__ hin, const int* __restrict__ src,
                          const int* __restrict__ dst, const int* __restrict__ et) {
    long gid = (long)blockIdx.x*blockDim.x + threadIdx.x;
    long e = gid >> 4;
    if (e >= Ee) return;
    int q = (int)(gid & 15);
    int s = __ldg(src + e);
    const float4 v = *(const float4*)(hin + (size_t)s*Dd + q*4);
    int seg = __ldg(dst + e)*Rr + __ldg(et + e);
    float* p = g_S + (size_t)seg*Dd + q*4;
    asm volatile("red.global.add.v4.f32 [%0], {%1, %2, %3, %4};"
                 :: "l"(p), "f"(v.x), "f"(v.y), "f"(v.z), "f"(v.w) : "memory");
}

// ---------------------------------------------------------------------------
// 4. transform: out[n] = h[n] + relu([S[n]*inv | h[n]] @ [W;Wroot] + b)
//    GEMM M=100000, N=64, K=576. Full weight (147 KB) in SMEM, 64-node tile
//    per block, thread = 4 nodes x 4 outputs, SW-pipelined A-chunk loads.
// ---------------------------------------------------------------------------
__global__ void __launch_bounds__(256, 1) transform_k(
    const float* __restrict__ W, const float* __restrict__ Wroot,
    const float* __restrict__ b, const float* __restrict__ hin,
    float* __restrict__ out) {
    extern __shared__ float sm[];
    float* sW   = sm;                   // KTOT*64 floats (147456 B)
    float* sA   = sm + KTOT*Dd;         // 8*64 floats  (chunk buffer)
    float* sInv = sA + 8*64;            // 64*8 floats
    const int tid = threadIdx.x;

    for (int i = tid; i < (Rr*Dd*Dd)/4; i += 256)
        ((float4*)sW)[i] = ((const float4*)W)[i];
    for (int i = tid; i < (Dd*Dd)/4; i += 256)
        ((float4*)(sW + Rr*Dd*Dd))[i] = ((const float4*)Wroot)[i];

    const int node0 = blockIdx.x * 64;
    for (int i = tid; i < 64*Rr; i += 256) {
        int n = node0 + (i >> 3);
        sInv[i] = (n < Nn) ? g_inv[n*Rr + (i & 7)] : 0.f;
    }
    __syncthreads();

    const int jq = tid & 15;            // output quad (4 cols)
    const int nq = tid >> 4;            // node quad group
    const int lnn = tid >> 2;           // load: node 0..63
    const int lk2 = (tid & 3) * 2;      // load: k-pair 0,2,4,6
    const int ln  = node0 + lnn;

    float acc[4][4];
    #pragma unroll
    for (int i = 0; i < 4; i++) { acc[i][0]=0.f; acc[i][1]=0.f; acc[i][2]=0.f; acc[i][3]=0.f; }

    auto load_chunk = [&](int kc) -> float2 {
        float2 v = make_float2(0.f, 0.f);
        if (ln < Nn) {
            int kb = kc*8 + lk2;
            if (kc < 64) {
                float2 s2 = *(const float2*)(g_S + (size_t)ln*(Rr*Dd) + kb);
                float iv = sInv[lnn*8 + (kc >> 3)];
                v.x = s2.x*iv; v.y = s2.y*iv;
            } else {
                v = *(const float2*)(hin + (size_t)ln*Dd + (kb - 512));
            }
        }
        return v;
    };

    float2 cur = load_chunk(0);
    for (int kc = 0; kc < KTOT/8; kc++) {
        sA[lk2*64 + lnn]     = cur.x;
        sA[(lk2+1)*64 + lnn] = cur.y;
        __syncthreads();
        float2 nxt = make_float2(0.f, 0.f);
        if (kc + 1 < KTOT/8) nxt = load_chunk(kc + 1);   // in flight during compute
        const float* wb = sW + kc*8*Dd + jq*4;
        #pragma unroll
        for (int kk = 0; kk < 8; kk++) {
            float4 w = *(const float4*)(wb + kk*Dd);
            #pragma unroll
            for (int i = 0; i < 4; i++) {
                float a = sA[kk*64 + nq*4 + i];
                acc[i][0] = fmaf(a, w.x, acc[i][0]);
                acc[i][1] = fmaf(a, w.y, acc[i][1]);
                acc[i][2] = fmaf(a, w.z, acc[i][2]);
                acc[i][3] = fmaf(a, w.w, acc[i][3]);
            }
        }
        __syncthreads();
        cur = nxt;
    }

    float4 bv = *(const float4*)(b + jq*4);
    #pragma unroll
    for (int i = 0; i < 4; i++) {
        int n = node0 + nq*4 + i;
        if (n < Nn) {
            float4 hv = *(const float4*)(hin + (size_t)n*Dd + jq*4);
            float4 o;
            o.x = hv.x + fmaxf(acc[i][0] + bv.x, 0.f);
            o.y = hv.y + fmaxf(acc[i][1] + bv.y, 0.f);
            o.z = hv.z + fmaxf(acc[i][2] + bv.z, 0.f);
            o.w = hv.w + fmaxf(acc[i][3] + bv.w, 0.f);
            *(float4*)(out + (size_t)n*Dd + jq*4) = o;
        }
    }
}

// ---------------------------------------------------------------------------
extern "C" void kernel_launch(void* const* d_in, const int* in_sizes, int n_in,
                              void* d_out, int out_size) {
    const int*   x     = (const int*)d_in[0];
    const int*   eidx  = (const int*)d_in[1];
    const int*   et    = (const int*)d_in[2];
    const int*   ntype = (const int*)d_in[3];
    const float* props = (const float*)d_in[4];
    const float* nemb  = (const float*)d_in[5];
    const float* temb  = (const float*)d_in[6];
    const float* pw1   = (const float*)d_in[7];
    const float* pb1   = (const float*)d_in[8];
    const float* pw2   = (const float*)d_in[9];
    const float* pb2   = (const float*)d_in[10];
    const float* W1    = (const float*)d_in[11];
    const float* Wr1   = (const float*)d_in[12];
    const float* b1    = (const float*)d_in[13];
    const float* W2    = (const float*)d_in[14];
    const float* Wr2   = (const float*)d_in[15];
    const float* b2    = (const float*)d_in[16];
    float* out = (float*)d_out;
    const int* src = eidx;
    const int* dst = eidx + Ee;

    void *pS, *pcnt, *ph, *ph2;
    cudaGetSymbolAddress(&pS,   g_S);
    cudaGetSymbolAddress(&pcnt, g_cnt);
    cudaGetSymbolAddress(&ph,   g_h);
    cudaGetSymbolAddress(&ph2,  g_h2);
    float* h  = (float*)ph;
    float* h2 = (float*)ph2;

    size_t smem = (size_t)(KTOT*Dd + 8*64 + 64*Rr) * sizeof(float);
    cudaFuncSetAttribute(transform_k, cudaFuncAttributeMaxDynamicSharedMemorySize, (int)smem);

    const int scatter_blocks = (int)(((long)Ee*16 + 255) / 256);
    const int tile_blocks    = (Nn + 63) / 64;

    cudaMemsetAsync(pS,   0, sizeof(float)*(size_t)Nn*Rr*Dd);
    cudaMemsetAsync(pcnt, 0, sizeof(int)*Nn*Rr);
    count_k<<<(Ee+255)/256, 256>>>(dst, et);
    inv_k<<<(Nn*Rr+255)/256, 256>>>();
    mlp_k<<<1536, 256>>>(x, ntype, props, nemb, temb, pw1, pb1, pw2, pb2);

    // layer 1
    scatter_k<<<scatter_blocks, 256>>>(h, src, dst, et);
    transform_k<<<tile_blocks, 256, smem>>>(W1, Wr1, b1, h, h2);

    // layer 2
    cudaMemsetAsync(pS, 0, sizeof(float)*(size_t)Nn*Rr*Dd);
    scatter_k<<<scatter_blocks, 256>>>(h2, src, dst, et);
    transform_k<<<tile_blocks, 256, smem>>>(W2, Wr2, b2, h2, out);
}

// round 3
// speedup vs baseline: 1.7034x; 1.7034x over previous
#include <cuda_runtime.h>
#include <cstdint>

#define Nn 100000
#define Rr 8
#define Dd 64
#define Tt 16
#define Pp 32
#define Ee 1600000
#define KTOT 576            // 8*64 (relations) + 64 (root)
#define KS   512            // S part of K
#define NCH  36             // K chunks of 16
#define CH   16
#define PITCH 20            // floats per node row in sA (bank-conflict-free, 16B aligned)
#define TILE 128
#define NTILES ((Nn + TILE - 1) / TILE)   // 782

// Scratch (device globals: no allocations allowed)
__device__ float g_S[(size_t)Nn*KS];      // 204.8 MB per-(node,rel) mean-scaled sums
__device__ float g_h[(size_t)Nn*Dd];
__device__ float g_h2[(size_t)Nn*Dd];
__device__ int   g_cnt[Nn*Rr];
__device__ float g_inv[Nn*Rr];

// ---------------------------------------------------------------------------
__global__ void count_k(const int* __restrict__ dst, const int* __restrict__ et) {
    int e = blockIdx.x*blockDim.x + threadIdx.x;
    if (e < Ee) atomicAdd(&g_cnt[dst[e]*Rr + et[e]], 1);
}

__global__ void inv_k() {
    int i = blockIdx.x*blockDim.x + threadIdx.x;
    if (i < Nn*Rr) g_inv[i] = 1.0f / (float)max(g_cnt[i], 1);
}

// ---------------------------------------------------------------------------
// h0 = node_emb[x] + type_emb[node_type] + MLP(node_properties)
// ---------------------------------------------------------------------------
__global__ void mlp_k(const int* __restrict__ x, const int* __restrict__ ntype,
                      const float* __restrict__ props, const float* __restrict__ nemb,
                      const float* __restrict__ temb,
                      const float* __restrict__ w1, const float* __restrict__ b1,
                      const float* __restrict__ w2, const float* __restrict__ b2) {
    __shared__ float sw1[Pp*Dd];
    __shared__ float sw2[Dd*Dd];
    __shared__ float sb1[Dd], sb2[Dd];
    __shared__ float shid[4][Dd];
    for (int i = threadIdx.x; i < Pp*Dd; i += 256) sw1[i] = w1[i];
    for (int i = threadIdx.x; i < Dd*Dd; i += 256) sw2[i] = w2[i];
    if (threadIdx.x < Dd) { sb1[threadIdx.x] = b1[threadIdx.x]; sb2[threadIdx.x] = b2[threadIdx.x]; }
    __syncthreads();
    const int g = threadIdx.x >> 6, j = threadIdx.x & 63;
    for (int n0 = blockIdx.x*4; n0 < Nn; n0 += gridDim.x*4) {
        int n = n0 + g;
        float hj = 0.f;
        if (n < Nn) {
            hj = sb1[j];
            const float* pr = props + (size_t)n*Pp;
            #pragma unroll
            for (int p = 0; p < Pp; p++) hj = fmaf(__ldg(pr+p), sw1[p*Dd+j], hj);
            hj = fmaxf(hj, 0.f);
        }
        shid[g][j] = hj;
        __syncthreads();
        if (n < Nn) {
            float o = sb2[j];
            #pragma unroll
            for (int k = 0; k < Dd; k++) o = fmaf(shid[g][k], sw2[k*Dd+j], o);
            o += nemb[(size_t)x[n]*Dd + j] + temb[(size_t)ntype[n]*Dd + j];
            g_h[(size_t)n*Dd + j] = o;
        }
        __syncthreads();
    }
}

// ---------------------------------------------------------------------------
// scatter: S[dst*8+et, :] += inv[dst,et] * h[src, :]   (mean folded in)
// 16 threads/edge, red.global.add.v4
// ---------------------------------------------------------------------------
__global__ void scatter_k(const float* __restrict__ hin, const int* __restrict__ src,
                          const int* __restrict__ dst, const int* __restrict__ et) {
    long gid = (long)blockIdx.x*blockDim.x + threadIdx.x;
    long e = gid >> 4;
    if (e >= Ee) return;
    int q = (int)(gid & 15);
    int s = __ldg(src + e);
    int seg = __ldg(dst + e)*Rr + __ldg(et + e);
    float iv = __ldg(g_inv + seg);
    float4 v = *(const float4*)(hin + (size_t)s*Dd + q*4);
    v.x *= iv; v.y *= iv; v.z *= iv; v.w *= iv;
    float* p = g_S + (size_t)seg*Dd + q*4;
    asm volatile("red.global.add.v4.f32 [%0], {%1, %2, %3, %4};"
                 :: "l"(p), "f"(v.x), "f"(v.y), "f"(v.z), "f"(v.w) : "memory");
}

// ---------------------------------------------------------------------------
// transform: out[n] = h[n] + relu([Sbar[n] | h[n]] @ [W;Wroot] + b)
// Persistent blocks (grid=148). W (147KB) in SMEM once per SM.
// 128-node tiles, K-chunks of 16, 3-stage cp.async pipeline, 1 barrier/chunk.
// Thread = 8 nodes x 4 cols. FFMA-pipe-bound by design.
// ---------------------------------------------------------------------------
__device__ __forceinline__ void cp16(uint32_t dst, const void* src, int srcsz) {
    asm volatile("cp.async.cg.shared.global [%0], [%1], 16, %2;\n"
                 :: "r"(dst), "l"(src), "r"(srcsz));
}
__device__ __forceinline__ void cp_commit() {
    asm volatile("cp.async.commit_group;\n");
}
template<int N> __device__ __forceinline__ void cp_wait() {
    asm volatile("cp.async.wait_group %0;\n" :: "n"(N));
}

__global__ void __launch_bounds__(256, 1) transform_k(
    const float* __restrict__ W, const float* __restrict__ Wroot,
    const float* __restrict__ b, const float* __restrict__ hin,
    float* __restrict__ out) {
    extern __shared__ float sm[];
    float* sW = sm;                      // KTOT*64 = 36864 floats
    float* sA = sm + KTOT*Dd;            // 3 * 128 * PITCH floats
    const int tid = threadIdx.x;

    for (int i = tid; i < (KS*Dd)/4; i += 256)
        ((float4*)sW)[i] = ((const float4*)W)[i];
    for (int i = tid; i < (Dd*Dd)/4; i += 256)
        ((float4*)(sW + KS*Dd))[i] = ((const float4*)Wroot)[i];
    __syncthreads();

    const int jq = tid & 15;     // col quad: cols jq*4 .. jq*4+3
    const int ng = tid >> 4;     // node group: nodes ng*8 .. ng*8+7
    const uint32_t sA_u32 = (uint32_t)__cvta_generic_to_shared(sA);
    const float4 bv = __ldg((const float4*)b + jq);

    for (int tile = blockIdx.x; tile < NTILES; tile += gridDim.x) {
        const int node0 = tile * TILE;

        float acc[8][4];
        #pragma unroll
        for (int i = 0; i < 8; i++)
            { acc[i][0]=0.f; acc[i][1]=0.f; acc[i][2]=0.f; acc[i][3]=0.f; }

        // issue one 16-wide K-chunk into stage kc%3 (2 x 16B per thread)
        auto issue = [&](int kc) {
            const int stage = kc % 3;
            #pragma unroll
            for (int u = 0; u < 2; u++) {
                int idx  = tid + u*256;          // 0..511
                int nd   = idx >> 2;             // node within tile
                int part = idx & 3;              // float4 within chunk
                int n    = node0 + nd;
                int nc   = (n < Nn) ? n : (Nn - 1);
                const float* src = (kc < 32)
                    ? g_S + (size_t)nc*KS + kc*CH + part*4
                    : hin + (size_t)nc*Dd + (kc-32)*CH + part*4;
                uint32_t d = sA_u32 + (uint32_t)(((stage*TILE + nd)*PITCH + part*4) * 4);
                cp16(d, src, (n < Nn) ? 16 : 0);
            }
            cp_commit();
        };

        issue(0);
        for (int kc = 0; kc < NCH; kc++) {
            if (kc + 1 < NCH) { issue(kc + 1); cp_wait<1>(); }
            else              { cp_wait<0>(); }
            __syncthreads();
            const float* aB = sA + (kc % 3)*TILE*PITCH + ng*8*PITCH;
            const float* wB = sW + kc*CH*Dd + jq*4;
            #pragma unroll
            for (int k = 0; k < CH; k++) {
                float4 w = *(const float4*)(wB + k*Dd);
                #pragma unroll
                for (int i = 0; i < 8; i++) {
                    float a = aB[i*PITCH + k];
                    acc[i][0] = fmaf(a, w.x, acc[i][0]);
                    acc[i][1] = fmaf(a, w.y, acc[i][1]);
                    acc[i][2] = fmaf(a, w.z, acc[i][2]);
                    acc[i][3] = fmaf(a, w.w, acc[i][3]);
                }
            }
            // no trailing barrier: 3-stage ring + per-iter barrier keeps
            // writes >=2 chunks away from any reader
        }

        #pragma unroll
        for (int i = 0; i < 8; i++) {
            int n = node0 + ng*8 + i;
            if (n < Nn) {
                float4 hv = *(const float4*)(hin + (size_t)n*Dd + jq*4);
                float4 o;
                o.x = hv.x + fmaxf(acc[i][0] + bv.x, 0.f);
                o.y = hv.y + fmaxf(acc[i][1] + bv.y, 0.f);
                o.z = hv.z + fmaxf(acc[i][2] + bv.z, 0.f);
                o.w = hv.w + fmaxf(acc[i][3] + bv.w, 0.f);
                *(float4*)(out + (size_t)n*Dd + jq*4) = o;
            }
        }
        __syncthreads();   // sA stage-0 rewrite in next tile vs slowest reader
    }
}

// ---------------------------------------------------------------------------
extern "C" void kernel_launch(void* const* d_in, const int* in_sizes, int n_in,
                              void* d_out, int out_size) {
    const int*   x     = (const int*)d_in[0];
    const int*   eidx  = (const int*)d_in[1];
    const int*   et    = (const int*)d_in[2];
    const int*   ntype = (const int*)d_in[3];
    const float* props = (const float*)d_in[4];
    const float* nemb  = (const float*)d_in[5];
    const float* temb  = (const float*)d_in[6];
    const float* pw1   = (const float*)d_in[7];
    const float* pb1   = (const float*)d_in[8];
    const float* pw2   = (const float*)d_in[9];
    const float* pb2   = (const float*)d_in[10];
    const float* W1    = (const float*)d_in[11];
    const float* Wr1   = (const float*)d_in[12];
    const float* b1    = (const float*)d_in[13];
    const float* W2    = (const float*)d_in[14];
    const float* Wr2   = (const float*)d_in[15];
    const float* b2    = (const float*)d_in[16];
    float* out = (float*)d_out;
    const int* src = eidx;
    const int* dst = eidx + Ee;

    void *pS, *pcnt, *ph, *ph2;
    cudaGetSymbolAddress(&pS,   g_S);
    cudaGetSymbolAddress(&pcnt, g_cnt);
    cudaGetSymbolAddress(&ph,   g_h);
    cudaGetSymbolAddress(&ph2,  g_h2);
    float* h  = (float*)ph;
    float* h2 = (float*)ph2;

    size_t smem = (size_t)(KTOT*Dd + 3*TILE*PITCH) * sizeof(float);
    cudaFuncSetAttribute(transform_k, cudaFuncAttributeMaxDynamicSharedMemorySize, (int)smem);

    const int scatter_blocks = (int)(((long)Ee*16 + 255) / 256);

    cudaMemsetAsync(pS,   0, sizeof(float)*(size_t)Nn*KS);
    cudaMemsetAsync(pcnt, 0, sizeof(int)*Nn*Rr);
    count_k<<<(Ee+255)/256, 256>>>(dst, et);
    inv_k<<<(Nn*Rr+255)/256, 256>>>();
    mlp_k<<<1536, 256>>>(x, ntype, props, nemb, temb, pw1, pb1, pw2, pb2);

    // layer 1
    scatter_k<<<scatter_blocks, 256>>>(h, src, dst, et);
    transform_k<<<148, 256, smem>>>(W1, Wr1, b1, h, h2);

    // layer 2
    cudaMemsetAsync(pS, 0, sizeof(float)*(size_t)Nn*KS);
    scatter_k<<<scatter_blocks, 256>>>(h2, src, dst, et);
    transform_k<<<148, 256, smem>>>(W2, Wr2, b2, h2, out);
}

// round 4
// speedup vs baseline: 2.2127x; 1.2989x over previous
#include <cuda_runtime.h>
#include <cstdint>

#define Nn 100000
#define Rr 8
#define Dd 64
#define Tt 16
#define Pp 32
#define Ee 1600000
#define KTOT 576            // 8*64 (relations) + 64 (root)
#define KS   512            // S part of K
#define TILE 128
#define NTILES ((Nn + TILE - 1) / TILE)   // 782
#define KC    64            // K-chunk
#define NCHK  (KTOT/KC)     // 9
#define APITCH 68           // A smem row pitch (floats): 68%32=4 -> conflict-free frags
#define WPITCH 580          // Wt smem row pitch (floats): 580%32=4 -> conflict-free frags

// Scratch (device globals: no allocations allowed)
__device__ float g_S[(size_t)Nn*KS];      // per-(node,rel) mean-scaled sums
__device__ float g_h[(size_t)Nn*Dd];
__device__ float g_h2[(size_t)Nn*Dd];
__device__ int   g_cnt[Nn*Rr];
__device__ float g_inv[Nn*Rr];

// ---------------------------------------------------------------------------
__global__ void count_k(const int* __restrict__ dst, const int* __restrict__ et) {
    int e = blockIdx.x*blockDim.x + threadIdx.x;
    if (e < Ee) atomicAdd(&g_cnt[dst[e]*Rr + et[e]], 1);
}

__global__ void inv_k() {
    int i = blockIdx.x*blockDim.x + threadIdx.x;
    if (i < Nn*Rr) g_inv[i] = 1.0f / (float)max(g_cnt[i], 1);
}

// ---------------------------------------------------------------------------
// h0 = node_emb[x] + type_emb[node_type] + MLP(node_properties)
// ---------------------------------------------------------------------------
__global__ void mlp_k(const int* __restrict__ x, const int* __restrict__ ntype,
                      const float* __restrict__ props, const float* __restrict__ nemb,
                      const float* __restrict__ temb,
                      const float* __restrict__ w1, const float* __restrict__ b1,
                      const float* __restrict__ w2, const float* __restrict__ b2) {
    __shared__ float sw1[Pp*Dd];
    __shared__ float sw2[Dd*Dd];
    __shared__ float sb1[Dd], sb2[Dd];
    __shared__ float shid[4][Dd];
    for (int i = threadIdx.x; i < Pp*Dd; i += 256) sw1[i] = w1[i];
    for (int i = threadIdx.x; i < Dd*Dd; i += 256) sw2[i] = w2[i];
    if (threadIdx.x < Dd) { sb1[threadIdx.x] = b1[threadIdx.x]; sb2[threadIdx.x] = b2[threadIdx.x]; }
    __syncthreads();
    const int g = threadIdx.x >> 6, j = threadIdx.x & 63;
    for (int n0 = blockIdx.x*4; n0 < Nn; n0 += gridDim.x*4) {
        int n = n0 + g;
        float hj = 0.f;
        if (n < Nn) {
            hj = sb1[j];
            const float* pr = props + (size_t)n*Pp;
            #pragma unroll
            for (int p = 0; p < Pp; p++) hj = fmaf(__ldg(pr+p), sw1[p*Dd+j], hj);
            hj = fmaxf(hj, 0.f);
        }
        shid[g][j] = hj;
        __syncthreads();
        if (n < Nn) {
            float o = sb2[j];
            #pragma unroll
            for (int k = 0; k < Dd; k++) o = fmaf(shid[g][k], sw2[k*Dd+j], o);
            o += nemb[(size_t)x[n]*Dd + j] + temb[(size_t)ntype[n]*Dd + j];
            g_h[(size_t)n*Dd + j] = o;
        }
        __syncthreads();
    }
}

// ---------------------------------------------------------------------------
// scatter: S[dst*8+et, :] += inv[dst,et] * h[src, :]   (mean folded in)
// ---------------------------------------------------------------------------
__global__ void scatter_k(const float* __restrict__ hin, const int* __restrict__ src,
                          const int* __restrict__ dst, const int* __restrict__ et) {
    long gid = (long)blockIdx.x*blockDim.x + threadIdx.x;
    long e = gid >> 4;
    if (e >= Ee) return;
    int q = (int)(gid & 15);
    int s = __ldg(src + e);
    int seg = __ldg(dst + e)*Rr + __ldg(et + e);
    float iv = __ldg(g_inv + seg);
    float4 v = *(const float4*)(hin + (size_t)s*Dd + q*4);
    v.x *= iv; v.y *= iv; v.z *= iv; v.w *= iv;
    float* p = g_S + (size_t)seg*Dd + q*4;
    asm volatile("red.global.add.v4.f32 [%0], {%1, %2, %3, %4};"
                 :: "l"(p), "f"(v.x), "f"(v.y), "f"(v.z), "f"(v.w) : "memory");
}

// ---------------------------------------------------------------------------
// tf32 tensor-core transform:
//   out[n] = h[n] + relu([Sbar[n] | h[n]] @ [W;Wroot] + b)
// Persistent grid=148. Wt (tf32, transposed, 148KB) in SMEM once per block.
// 128-node tiles, K-chunks of 64, 2-stage cp.async, mma.sync.m16n8k8.tf32.
// 8 warps = 4(m) x 2(n); warp tile 32x32 = 2 m-frags x 4 n-frags.
// ---------------------------------------------------------------------------
__device__ __forceinline__ void cp16(uint32_t dst, const void* src) {
    asm volatile("cp.async.cg.shared.global [%0], [%1], 16;\n" :: "r"(dst), "l"(src));
}
__device__ __forceinline__ void cp_commit() { asm volatile("cp.async.commit_group;\n"); }
template<int N> __device__ __forceinline__ void cp_wait() {
    asm volatile("cp.async.wait_group %0;\n" :: "n"(N));
}
__device__ __forceinline__ uint32_t f2tf32(float x) {
    uint32_t r;
    asm("cvt.rna.tf32.f32 %0, %1;" : "=r"(r) : "f"(x));
    return r;
}
__device__ __forceinline__ void mma_tf32(float c[4], uint32_t a0, uint32_t a1,
                                         uint32_t a2, uint32_t a3,
                                         uint32_t b0, uint32_t b1) {
    asm volatile("mma.sync.aligned.m16n8k8.row.col.f32.tf32.tf32.f32 "
                 "{%0,%1,%2,%3}, {%4,%5,%6,%7}, {%8,%9}, {%0,%1,%2,%3};"
                 : "+f"(c[0]), "+f"(c[1]), "+f"(c[2]), "+f"(c[3])
                 : "r"(a0), "r"(a1), "r"(a2), "r"(a3), "r"(b0), "r"(b1));
}

__global__ void __launch_bounds__(256, 1) transform_k(
    const float* __restrict__ W, const float* __restrict__ Wroot,
    const float* __restrict__ b, const float* __restrict__ hin,
    float* __restrict__ out) {
    extern __shared__ float sm[];
    uint32_t* sWt = (uint32_t*)sm;            // [64][WPITCH] tf32, transposed
    float*    sA  = sm + 64*WPITCH;           // 2 stages x [128][APITCH]
    const int tid  = threadIdx.x;
    const int lane = tid & 31;
    const int wid  = tid >> 5;
    const int g    = lane >> 2;     // groupID
    const int tig  = lane & 3;      // thread in group
    const int wm   = wid & 3;       // warp m group (0..3) -> rows wm*32
    const int wn   = wid >> 2;      // warp n group (0..1) -> cols wn*32

    // Wt[n][k] = tf32(W[k][n]); W=(R,Din,Dout): k=r*64+i -> row k*64+n; Wroot: k=512+i
    for (int idx = tid; idx < KTOT*Dd; idx += 256) {
        int k = idx >> 6, n = idx & 63;
        float v = (k < KS) ? W[(size_t)k*Dd + n] : Wroot[(size_t)(k-KS)*Dd + n];
        sWt[n*WPITCH + k] = f2tf32(v);
    }
    __syncthreads();

    const uint32_t sA_u32 = (uint32_t)__cvta_generic_to_shared(sA);

    for (int tile = blockIdx.x; tile < NTILES; tile += gridDim.x) {
        const int node0 = tile * TILE;

        // issue one 64-float K-chunk for 128 nodes into stage kc&1
        auto issue = [&](int kc) {
            const int stage = kc & 1;
            #pragma unroll
            for (int u = 0; u < 8; u++) {
                int idx  = tid + u*256;          // 0..2047
                int nd   = idx >> 4;             // node within tile
                int part = idx & 15;             // 16B unit within 256B row
                int n    = node0 + nd;
                int nc   = (n < Nn) ? n : (Nn - 1);
                const float* src = (kc < 8)
                    ? g_S + (size_t)nc*KS + kc*KC + part*4
                    : hin + (size_t)nc*Dd + part*4;
                cp16(sA_u32 + (uint32_t)(((stage*TILE + nd)*APITCH + part*4) * 4), src);
            }
            cp_commit();
        };

        float acc[2][4][4];
        #pragma unroll
        for (int mf = 0; mf < 2; mf++)
            #pragma unroll
            for (int nf = 0; nf < 4; nf++)
                { acc[mf][nf][0]=0.f; acc[mf][nf][1]=0.f; acc[mf][nf][2]=0.f; acc[mf][nf][3]=0.f; }

        issue(0);
        cp_wait<0>(); __syncthreads();
        for (int kc = 0; kc < NCHK; kc++) {
            if (kc + 1 < NCHK) issue(kc + 1);           // stage (kc+1)&1 free (synced after kc-1)
            const float* aS = sA + (kc & 1)*TILE*APITCH;
            #pragma unroll
            for (int ks = 0; ks < KC/8; ks++) {
                const int kl = ks*8;                     // local k base
                const int kg = kc*KC + kl;               // global k base
                #pragma unroll
                for (int mf = 0; mf < 2; mf++) {
                    const float* ap = aS + (wm*32 + mf*16)*APITCH + kl;
                    uint32_t a0 = f2tf32(ap[ g     *APITCH + tig    ]);
                    uint32_t a1 = f2tf32(ap[(g + 8)*APITCH + tig    ]);
                    uint32_t a2 = f2tf32(ap[ g     *APITCH + tig + 4]);
                    uint32_t a3 = f2tf32(ap[(g + 8)*APITCH + tig + 4]);
                    #pragma unroll
                    for (int nf = 0; nf < 4; nf++) {
                        const uint32_t* bp = sWt + (wn*32 + nf*8 + g)*WPITCH + kg + tig;
                        mma_tf32(acc[mf][nf], a0, a1, a2, a3, bp[0], bp[4]);
                    }
                }
            }
            __syncthreads();                             // done reading stage kc&1
            if (kc + 1 < NCHK) { cp_wait<0>(); __syncthreads(); }  // stage kc+1 ready
        }

        // epilogue: out = h + relu(acc + bias)
        #pragma unroll
        for (int mf = 0; mf < 2; mf++) {
            #pragma unroll
            for (int nf = 0; nf < 4; nf++) {
                int col = wn*32 + nf*8 + tig*2;
                float2 bv = *(const float2*)(b + col);
                #pragma unroll
                for (int half = 0; half < 2; half++) {
                    int r = node0 + wm*32 + mf*16 + g + half*8;
                    if (r < Nn) {
                        float2 hv = *(const float2*)(hin + (size_t)r*Dd + col);
                        float2 o;
                        o.x = hv.x + fmaxf(acc[mf][nf][half*2 + 0] + bv.x, 0.f);
                        o.y = hv.y + fmaxf(acc[mf][nf][half*2 + 1] + bv.y, 0.f);
                        *(float2*)(out + (size_t)r*Dd + col) = o;
                    }
                }
            }
        }
        // stage 0 was last read in chunk kc=8 whose trailing sync already ran;
        // epilogue doesn't touch sA, so next tile's issue(0) is safe.
    }
}

// ---------------------------------------------------------------------------
extern "C" void kernel_launch(void* const* d_in, const int* in_sizes, int n_in,
                              void* d_out, int out_size) {
    const int*   x     = (const int*)d_in[0];
    const int*   eidx  = (const int*)d_in[1];
    const int*   et    = (const int*)d_in[2];
    const int*   ntype = (const int*)d_in[3];
    const float* props = (const float*)d_in[4];
    const float* nemb  = (const float*)d_in[5];
    const float* temb  = (const float*)d_in[6];
    const float* pw1   = (const float*)d_in[7];
    const float* pb1   = (const float*)d_in[8];
    const float* pw2   = (const float*)d_in[9];
    const float* pb2   = (const float*)d_in[10];
    const float* W1    = (const float*)d_in[11];
    const float* Wr1   = (const float*)d_in[12];
    const float* b1    = (const float*)d_in[13];
    const float* W2    = (const float*)d_in[14];
    const float* Wr2   = (const float*)d_in[15];
    const float* b2    = (const float*)d_in[16];
    float* out = (float*)d_out;
    const int* src = eidx;
    const int* dst = eidx + Ee;

    void *pS, *pcnt, *ph, *ph2;
    cudaGetSymbolAddress(&pS,   g_S);
    cudaGetSymbolAddress(&pcnt, g_cnt);
    cudaGetSymbolAddress(&ph,   g_h);
    cudaGetSymbolAddress(&ph2,  g_h2);
    float* h  = (float*)ph;
    float* h2 = (float*)ph2;

    size_t smem = (size_t)(64*WPITCH + 2*TILE*APITCH) * sizeof(float);  // 218112 B
    cudaFuncSetAttribute(transform_k, cudaFuncAttributeMaxDynamicSharedMemorySize, (int)smem);

    const int scatter_blocks = (int)(((long)Ee*16 + 255) / 256);

    cudaMemsetAsync(pS,   0, sizeof(float)*(size_t)Nn*KS);
    cudaMemsetAsync(pcnt, 0, sizeof(int)*Nn*Rr);
    count_k<<<(Ee+255)/256, 256>>>(dst, et);
    inv_k<<<(Nn*Rr+255)/256, 256>>>();
    mlp_k<<<1536, 256>>>(x, ntype, props, nemb, temb, pw1, pb1, pw2, pb2);

    // layer 1
    scatter_k<<<scatter_blocks, 256>>>(h, src, dst, et);
    transform_k<<<148, 256, smem>>>(W1, Wr1, b1, h, h2);

    // layer 2
    cudaMemsetAsync(pS, 0, sizeof(float)*(size_t)Nn*KS);
    scatter_k<<<scatter_blocks, 256>>>(h2, src, dst, et);
    transform_k<<<148, 256, smem>>>(W2, Wr2, b2, h2, out);
}

// round 7
// speedup vs baseline: 2.2310x; 1.0083x over previous
#include <cuda_runtime.h>
#include <cstdint>

#define Nn 100000
#define Rr 8
#define Dd 64
#define Tt 16
#define Pp 32
#define Ee 1600000
#define KTOT 576            // 8*64 (relations) + 64 (root)
#define KS   512            // S part of K
#define TILE 128
#define NTILES ((Nn + TILE - 1) / TILE)   // 782
#define KC    32            // K-chunk width
#define NCHK  18            // 16 S chunks + 2 h chunks
#define NSTG  4             // pipeline stages
#define APITCH 36           // A smem pitch (floats): 36%32=4 -> conflict-free frags
#define WPITCH 580          // Wt smem pitch (floats): 580%32=4 -> conflict-free frags

// Scratch (device globals: no allocations allowed)
__device__ float g_S[(size_t)Nn*KS];      // per-(node,rel) mean-scaled sums
__device__ float g_h[(size_t)Nn*Dd];
__device__ float g_h2[(size_t)Nn*Dd];
__device__ int   g_cnt[Nn*Rr];
__device__ float g_inv[Nn*Rr];

// ---------------------------------------------------------------------------
__global__ void count_k(const int* __restrict__ dst, const int* __restrict__ et) {
    int e = blockIdx.x*blockDim.x + threadIdx.x;
    if (e < Ee) atomicAdd(&g_cnt[dst[e]*Rr + et[e]], 1);
}

__global__ void inv_k() {
    int i = blockIdx.x*blockDim.x + threadIdx.x;
    if (i < Nn*Rr) g_inv[i] = 1.0f / (float)max(g_cnt[i], 1);
}

// ---------------------------------------------------------------------------
// h0 = node_emb[x] + type_emb[node_type] + MLP(node_properties)
// ---------------------------------------------------------------------------
__global__ void mlp_k(const int* __restrict__ x, const int* __restrict__ ntype,
                      const float* __restrict__ props, const float* __restrict__ nemb,
                      const float* __restrict__ temb,
                      const float* __restrict__ w1, const float* __restrict__ b1,
                      const float* __restrict__ w2, const float* __restrict__ b2) {
    __shared__ float sw1[Pp*Dd];
    __shared__ float sw2[Dd*Dd];
    __shared__ float sb1[Dd], sb2[Dd];
    __shared__ float shid[4][Dd];
    for (int i = threadIdx.x; i < Pp*Dd; i += 256) sw1[i] = w1[i];
    for (int i = threadIdx.x; i < Dd*Dd; i += 256) sw2[i] = w2[i];
    if (threadIdx.x < Dd) { sb1[threadIdx.x] = b1[threadIdx.x]; sb2[threadIdx.x] = b2[threadIdx.x]; }
    __syncthreads();
    const int g = threadIdx.x >> 6, j = threadIdx.x & 63;
    for (int n0 = blockIdx.x*4; n0 < Nn; n0 += gridDim.x*4) {
        int n = n0 + g;
        float hj = 0.f;
        if (n < Nn) {
            hj = sb1[j];
            const float* pr = props + (size_t)n*Pp;
            #pragma unroll
            for (int p = 0; p < Pp; p++) hj = fmaf(__ldg(pr+p), sw1[p*Dd+j], hj);
            hj = fmaxf(hj, 0.f);
        }
        shid[g][j] = hj;
        __syncthreads();
        if (n < Nn) {
            float o = sb2[j];
            #pragma unroll
            for (int k = 0; k < Dd; k++) o = fmaf(shid[g][k], sw2[k*Dd+j], o);
            o += nemb[(size_t)x[n]*Dd + j] + temb[(size_t)ntype[n]*Dd + j];
            g_h[(size_t)n*Dd + j] = o;
        }
        __syncthreads();
    }
}

// ---------------------------------------------------------------------------
// scatter: S[dst*8+et, :] += inv[dst,et] * h[src, :]   (mean folded in)
// ---------------------------------------------------------------------------
__global__ void scatter_k(const float* __restrict__ hin, const int* __restrict__ src,
                          const int* __restrict__ dst, const int* __restrict__ et) {
    long gid = (long)blockIdx.x*blockDim.x + threadIdx.x;
    long e = gid >> 4;
    if (e >= Ee) return;
    int q = (int)(gid & 15);
    int s = __ldg(src + e);
    int seg = __ldg(dst + e)*Rr + __ldg(et + e);
    float iv = __ldg(g_inv + seg);
    float4 v = *(const float4*)(hin + (size_t)s*Dd + q*4);
    v.x *= iv; v.y *= iv; v.z *= iv; v.w *= iv;
    float* p = g_S + (size_t)seg*Dd + q*4;
    asm volatile("red.global.add.v4.f32 [%0], {%1, %2, %3, %4};"
                 :: "l"(p), "f"(v.x), "f"(v.y), "f"(v.z), "f"(v.w) : "memory");
}

// ---------------------------------------------------------------------------
// tf32 tensor-core transform, deep cp.async pipeline:
//   out[n] = h[n] + relu([Sbar[n] | h[n]] @ [W;Wroot] + b)
// Persistent grid=148. Wt (tf32, transposed, 145KB) in SMEM once per block.
// 128-node tiles, 32-wide K-chunks, 4-stage ring, wait_group<2> keeps two
// copies in flight -> copy fully overlapped, kernel DRAM-bound.
// 8 warps = 4(m) x 2(n); warp tile 32x32.
// ---------------------------------------------------------------------------
__device__ __forceinline__ uint32_t f2tf32(float x) {
    uint32_t r;
    asm("cvt.rna.tf32.f32 %0, %1;" : "=r"(r) : "f"(x));
    return r;
}
__device__ __forceinline__ void mma_tf32(float c[4], uint32_t a0, uint32_t a1,
                                         uint32_t a2, uint32_t a3,
                                         uint32_t b0, uint32_t b1) {
    asm volatile("mma.sync.aligned.m16n8k8.row.col.f32.tf32.tf32.f32 "
                 "{%0,%1,%2,%3}, {%4,%5,%6,%7}, {%8,%9}, {%0,%1,%2,%3};"
                 : "+f"(c[0]), "+f"(c[1]), "+f"(c[2]), "+f"(c[3])
                 : "r"(a0), "r"(a1), "r"(a2), "r"(a3), "r"(b0), "r"(b1));
}
__device__ __forceinline__ void cp16(uint32_t dst, const void* src) {
    asm volatile("cp.async.cg.shared.global [%0], [%1], 16;\n" :: "r"(dst), "l"(src));
}
__device__ __forceinline__ void cp_commit() { asm volatile("cp.async.commit_group;\n"); }
template<int N> __device__ __forceinline__ void cp_wait() {
    asm volatile("cp.async.wait_group %0;\n" :: "n"(N));
}

__global__ void __launch_bounds__(256, 1) transform_k(
    const float* __restrict__ W, const float* __restrict__ Wroot,
    const float* __restrict__ b, const float* __restrict__ hin,
    float* __restrict__ out) {
    extern __shared__ float sm[];
    uint32_t* sWt = (uint32_t*)sm;            // [64][WPITCH] tf32, transposed
    float*    sA  = sm + 64*WPITCH;           // NSTG stages x [128][APITCH]
    const int tid  = threadIdx.x;
    const int lane = tid & 31;
    const int wid  = tid >> 5;
    const int g    = lane >> 2;     // groupID
    const int tig  = lane & 3;      // thread in group
    const int wm   = wid & 3;       // warp m group -> rows wm*32
    const int wn   = wid >> 2;      // warp n group -> cols wn*32

    // Wt[n][k] = tf32(W[k][n]); k=r*64+i for W (R,Din,Dout); Wroot at k>=512
    for (int idx = tid; idx < KTOT*Dd; idx += 256) {
        int k = idx >> 6, n = idx & 63;
        float v = (k < KS) ? W[(size_t)k*Dd + n] : Wroot[(size_t)(k-KS)*Dd + n];
        sWt[n*WPITCH + k] = f2tf32(v);
    }
    __syncthreads();

    const uint32_t sA_u32 = (uint32_t)__cvta_generic_to_shared(sA);

    for (int tile = blockIdx.x; tile < NTILES; tile += gridDim.x) {
        const int node0 = tile * TILE;

        // issue one 32-wide K-chunk (16KB) into stage kc%NSTG; 4 x cp16/thread
        auto issue = [&](int kc) {
            const int stage = kc & (NSTG - 1);
            #pragma unroll
            for (int u = 0; u < 4; u++) {
                int idx  = tid + u*256;          // 0..1023
                int nd   = idx >> 3;             // node within tile
                int part = idx & 7;              // 16B unit within 128B row
                int n    = node0 + nd;
                int nc   = (n < Nn) ? n : (Nn - 1);
                const float* src = (kc < 16)
                    ? g_S + (size_t)nc*KS + kc*KC + part*4
                    : hin + (size_t)nc*Dd + (kc-16)*KC + part*4;
                cp16(sA_u32 + (uint32_t)(((stage*TILE + nd)*APITCH + part*4) * 4), src);
            }
            cp_commit();
        };

        float acc[2][4][4];
        #pragma unroll
        for (int mf = 0; mf < 2; mf++)
            #pragma unroll
            for (int nf = 0; nf < 4; nf++)
                { acc[mf][nf][0]=0.f; acc[mf][nf][1]=0.f; acc[mf][nf][2]=0.f; acc[mf][nf][3]=0.f; }

        issue(0); issue(1); issue(2);
        for (int kc = 0; kc < NCHK; kc++) {
            cp_wait<2>();                // group kc complete (<=2 newer pending)
            __syncthreads();             // make stage kc%NSTG visible to all
            const float* aS = sA + (kc & (NSTG - 1))*TILE*APITCH;
            #pragma unroll
            for (int ks = 0; ks < KC/8; ks++) {
                const int kl = ks*8;
                const int kg = kc*KC + kl;
                #pragma unroll
                for (int mf = 0; mf < 2; mf++) {
                    const float* ap = aS + (wm*32 + mf*16)*APITCH + kl;
                    uint32_t a0 = f2tf32(ap[ g     *APITCH + tig    ]);
                    uint32_t a1 = f2tf32(ap[(g + 8)*APITCH + tig    ]);
                    uint32_t a2 = f2tf32(ap[ g     *APITCH + tig + 4]);
                    uint32_t a3 = f2tf32(ap[(g + 8)*APITCH + tig + 4]);
                    #pragma unroll
                    for (int nf = 0; nf < 4; nf++) {
                        const uint32_t* bp = sWt + (wn*32 + nf*8 + g)*WPITCH + kg + tig;
                        mma_tf32(acc[mf][nf], a0, a1, a2, a3, bp[0], bp[4]);
                    }
                }
            }
            __syncthreads();             // all warps done reading stage kc%NSTG
            if (kc + 3 < NCHK) issue(kc + 3);   // reuse stage (kc-1)%NSTG
            else               cp_commit();     // empty group keeps wait<2> uniform
        }

        // epilogue: out = h + relu(acc + bias)
        #pragma unroll
        for (int mf = 0; mf < 2; mf++) {
            #pragma unroll
            for (int nf = 0; nf < 4; nf++) {
                int col = wn*32 + nf*8 + tig*2;
                float2 bv = *(const float2*)(b + col);
                #pragma unroll
                for (int half = 0; half < 2; half++) {
                    int r = node0 + wm*32 + mf*16 + g + half*8;
                    if (r < Nn) {
                        float2 hv = *(const float2*)(hin + (size_t)r*Dd + col);
                        float2 o;
                        o.x = hv.x + fmaxf(acc[mf][nf][half*2 + 0] + bv.x, 0.f);
                        o.y = hv.y + fmaxf(acc[mf][nf][half*2 + 1] + bv.y, 0.f);
                        *(float2*)(out + (size_t)r*Dd + col) = o;
                    }
                }
            }
        }
    }
}

// ---------------------------------------------------------------------------
extern "C" void kernel_launch(void* const* d_in, const int* in_sizes, int n_in,
                              void* d_out, int out_size) {
    const int*   x     = (const int*)d_in[0];
    const int*   eidx  = (const int*)d_in[1];
    const int*   et    = (const int*)d_in[2];
    const int*   ntype = (const int*)d_in[3];
    const float* props = (const float*)d_in[4];
    const float* nemb  = (const float*)d_in[5];
    const float* temb  = (const float*)d_in[6];
    const float* pw1   = (const float*)d_in[7];
    const float* pb1   = (const float*)d_in[8];
    const float* pw2   = (const float*)d_in[9];
    const float* pb2   = (const float*)d_in[10];
    const float* W1    = (const float*)d_in[11];
    const float* Wr1   = (const float*)d_in[12];
    const float* b1    = (const float*)d_in[13];
    const float* W2    = (const float*)d_in[14];
    const float* Wr2   = (const float*)d_in[15];
    const float* b2    = (const float*)d_in[16];
    float* out = (float*)d_out;
    const int* src = eidx;
    const int* dst = eidx + Ee;

    void *pS, *pcnt, *ph, *ph2;
    cudaGetSymbolAddress(&pS,   g_S);
    cudaGetSymbolAddress(&pcnt, g_cnt);
    cudaGetSymbolAddress(&ph,   g_h);
    cudaGetSymbolAddress(&ph2,  g_h2);
    float* h  = (float*)ph;
    float* h2 = (float*)ph2;

    size_t smem = (size_t)(64*WPITCH + NSTG*TILE*APITCH) * sizeof(float);  // 222208 B
    cudaFuncSetAttribute(transform_k, cudaFuncAttributeMaxDynamicSharedMemorySize, (int)smem);

    const int scatter_blocks = (int)(((long)Ee*16 + 255) / 256);

    cudaMemsetAsync(pS,   0, sizeof(float)*(size_t)Nn*KS);
    cudaMemsetAsync(pcnt, 0, sizeof(int)*Nn*Rr);
    count_k<<<(Ee+255)/256, 256>>>(dst, et);
    inv_k<<<(Nn*Rr+255)/256, 256>>>();
    mlp_k<<<1536, 256>>>(x, ntype, props, nemb, temb, pw1, pb1, pw2, pb2);

    // layer 1
    scatter_k<<<scatter_blocks, 256>>>(h, src, dst, et);
    transform_k<<<148, 256, smem>>>(W1, Wr1, b1, h, h2);

    // layer 2
    cudaMemsetAsync(pS, 0, sizeof(float)*(size_t)Nn*KS);
    scatter_k<<<scatter_blocks, 256>>>(h2, src, dst, et);
    transform_k<<<148, 256, smem>>>(W2, Wr2, b2, h2, out);
}

// round 9
// speedup vs baseline: 2.5574x; 1.1463x over previous
#include <cuda_runtime.h>
#include <cstdint>

#define Nn 100000
#define Rr 8
#define Dd 64
#define Tt 16
#define Pp 32
#define Ee 1600000
#define NR (Nn*Rr)          // 800000 segments
#define KTOT 576            // 8*64 (relations) + 64 (root)
#define KS   512            // S part of K
#define TILE 128
#define NTILES ((Nn + TILE - 1) / TILE)   // 782
#define KC    32            // K-chunk width
#define NCHK  18            // 16 S chunks + 2 h chunks
#define NSTG  4             // pipeline stages
#define APITCH 36           // A smem pitch (floats): 36%32=4 -> conflict-free frags
#define WPITCH 580          // Wt smem pitch (floats): 580%32=4 -> conflict-free frags
#define SCAN_BLKS ((NR + 1023) / 1024)    // 782

// Scratch (device globals: no allocations allowed)
__device__ float g_S[(size_t)Nn*KS];      // per-(node,rel) mean-scaled sums
__device__ float g_h[(size_t)Nn*Dd];
__device__ float g_h2[(size_t)Nn*Dd];
__device__ int   g_cnt[NR];
__device__ float g_inv[NR];
__device__ int   g_off[NR + 1];           // CSR offsets
__device__ int   g_cur[NR];               // fill cursors
__device__ int   g_esrc[Ee];              // src ids sorted by (dst,rel)
__device__ int   g_bsum[SCAN_BLKS];
__device__ int   g_bbase[SCAN_BLKS];

// ---------------------------------------------------------------------------
__global__ void count_k(const int* __restrict__ dst, const int* __restrict__ et) {
    int e = blockIdx.x*blockDim.x + threadIdx.x;
    if (e < Ee) atomicAdd(&g_cnt[dst[e]*Rr + et[e]], 1);
}

__global__ void inv_k() {
    int i = blockIdx.x*blockDim.x + threadIdx.x;
    if (i < NR) g_inv[i] = 1.0f / (float)max(g_cnt[i], 1);
}

// ---------------------------------------------------------------------------
// exclusive scan of g_cnt -> g_off  (3 kernels, 1024 elems per block)
// ---------------------------------------------------------------------------
__device__ __forceinline__ int blk_excl_scan_1024(const int* in, int* out,
                                                  int base, int nmax) {
    __shared__ int swarp[8];
    const int t = threadIdx.x, lane = t & 31, w = t >> 5;
    int idx = base + t*4;
    int a0 = (idx+0 < nmax) ? in[idx+0] : 0;
    int a1 = (idx+1 < nmax) ? in[idx+1] : 0;
    int a2 = (idx+2 < nmax) ? in[idx+2] : 0;
    int a3 = (idx+3 < nmax) ? in[idx+3] : 0;
    int tsum = a0 + a1 + a2 + a3;
    int v = tsum;
    #pragma unroll
    for (int d = 1; d < 32; d <<= 1) {
        int u = __shfl_up_sync(0xffffffffu, v, d);
        if (lane >= d) v += u;
    }
    if (lane == 31) swarp[w] = v;
    __syncthreads();
    if (t == 0) { int r = 0; for (int i = 0; i < 8; i++) { int q = swarp[i]; swarp[i] = r; r += q; } }
    __syncthreads();
    int e0 = swarp[w] + (v - tsum);
    if (idx+0 < nmax) out[idx+0] = e0;
    if (idx+1 < nmax) out[idx+1] = e0 + a0;
    if (idx+2 < nmax) out[idx+2] = e0 + a0 + a1;
    if (idx+3 < nmax) out[idx+3] = e0 + a0 + a1 + a2;
    return swarp[7] + ((w == 7) ? v : 0);   // valid for t==255
}

__global__ void scan1_k() {
    int total = blk_excl_scan_1024(g_cnt, g_off, blockIdx.x*1024, NR);
    if (threadIdx.x == 255) g_bsum[blockIdx.x] = total;
}
__global__ void scan2_k() {      // single block over SCAN_BLKS (<=1024)
    blk_excl_scan_1024(g_bsum, g_bbase, 0, SCAN_BLKS);
}
__global__ void scan3_k() {
    int i = blockIdx.x*blockDim.x + threadIdx.x;
    if (i < NR) g_off[i] += g_bbase[i >> 10];
    if (i == 0) g_off[NR] = Ee;
}

// counting-sort src ids by segment (pos bound-checked defensively)
__global__ void fill_k(const int* __restrict__ src, const int* __restrict__ dst,
                       const int* __restrict__ et) {
    int e = blockIdx.x*blockDim.x + threadIdx.x;
    if (e < Ee) {
        int seg = dst[e]*Rr + et[e];
        int pos = g_off[seg] + atomicAdd(&g_cur[seg], 1);
        if (pos >= 0 && pos < Ee) g_esrc[pos] = src[e];
    }
}

// ---------------------------------------------------------------------------
// h0 = node_emb[x] + type_emb[node_type] + MLP(node_properties)
// ---------------------------------------------------------------------------
__global__ void mlp_k(const int* __restrict__ x, const int* __restrict__ ntype,
                      const float* __restrict__ props, const float* __restrict__ nemb,
                      const float* __restrict__ temb,
                      const float* __restrict__ w1, const float* __restrict__ b1,
                      const float* __restrict__ w2, const float* __restrict__ b2) {
    __shared__ float sw1[Pp*Dd];
    __shared__ float sw2[Dd*Dd];
    __shared__ float sb1[Dd], sb2[Dd];
    __shared__ float shid[4][Dd];
    for (int i = threadIdx.x; i < Pp*Dd; i += 256) sw1[i] = w1[i];
    for (int i = threadIdx.x; i < Dd*Dd; i += 256) sw2[i] = w2[i];
    if (threadIdx.x < Dd) { sb1[threadIdx.x] = b1[threadIdx.x]; sb2[threadIdx.x] = b2[threadIdx.x]; }
    __syncthreads();
    const int g = threadIdx.x >> 6, j = threadIdx.x & 63;
    for (int n0 = blockIdx.x*4; n0 < Nn; n0 += gridDim.x*4) {
        int n = n0 + g;
        float hj = 0.f;
        if (n < Nn) {
            hj = sb1[j];
            const float* pr = props + (size_t)n*Pp;
            #pragma unroll
            for (int p = 0; p < Pp; p++) hj = fmaf(__ldg(pr+p), sw1[p*Dd+j], hj);
            hj = fmaxf(hj, 0.f);
        }
        shid[g][j] = hj;
        __syncthreads();
        if (n < Nn) {
            float o = sb2[j];
            #pragma unroll
            for (int k = 0; k < Dd; k++) o = fmaf(shid[g][k], sw2[k*Dd+j], o);
            o += nemb[(size_t)x[n]*Dd + j] + temb[(size_t)ntype[n]*Dd + j];
            g_h[(size_t)n*Dd + j] = o;
        }
        __syncthreads();
    }
}

// ---------------------------------------------------------------------------
// segmented sum: S[seg,:] = inv[seg] * sum_{e in seg} h[esrc[e], :]
// warp per segment; lane covers 2 floats; no atomics, no memset, writes once.
// ---------------------------------------------------------------------------
__global__ void __launch_bounds__(256) seg_sum_k(const float* __restrict__ hin) {
    const int lane = threadIdx.x & 31;
    const int warp = (blockIdx.x*256 + threadIdx.x) >> 5;
    const int nwarp = (gridDim.x*256) >> 5;
    for (int seg = warp; seg < NR; seg += nwarp) {
        int beg = __ldg(g_off + seg), end = __ldg(g_off + seg + 1);
        float2 acc = make_float2(0.f, 0.f);
        for (int e = beg; e < end; e++) {
            int s = __ldg(g_esrc + e);
            float2 v = *(const float2*)(hin + (size_t)s*Dd + lane*2);
            acc.x += v.x; acc.y += v.y;
        }
        float iv = __ldg(g_inv + seg);
        acc.x *= iv; acc.y *= iv;
        *(float2*)(g_S + (size_t)seg*Dd + lane*2) = acc;
    }
}

// ---------------------------------------------------------------------------
// tf32 tensor-core transform (unchanged from R7 known-passing version)
// ---------------------------------------------------------------------------
__device__ __forceinline__ uint32_t f2tf32(float x) {
    uint32_t r;
    asm("cvt.rna.tf32.f32 %0, %1;" : "=r"(r) : "f"(x));
    return r;
}
__device__ __forceinline__ void mma_tf32(float c[4], uint32_t a0, uint32_t a1,
                                         uint32_t a2, uint32_t a3,
                                         uint32_t b0, uint32_t b1) {
    asm volatile("mma.sync.aligned.m16n8k8.row.col.f32.tf32.tf32.f32 "
                 "{%0,%1,%2,%3}, {%4,%5,%6,%7}, {%8,%9}, {%0,%1,%2,%3};"
                 : "+f"(c[0]), "+f"(c[1]), "+f"(c[2]), "+f"(c[3])
                 : "r"(a0), "r"(a1), "r"(a2), "r"(a3), "r"(b0), "r"(b1));
}
__device__ __forceinline__ void cp16(uint32_t dst, const void* src) {
    asm volatile("cp.async.cg.shared.global [%0], [%1], 16;\n" :: "r"(dst), "l"(src));
}
__device__ __forceinline__ void cp_commit() { asm volatile("cp.async.commit_group;\n"); }
template<int N> __device__ __forceinline__ void cp_wait() {
    asm volatile("cp.async.wait_group %0;\n" :: "n"(N));
}

__global__ void __launch_bounds__(256, 1) transform_k(
    const float* __restrict__ W, const float* __restrict__ Wroot,
    const float* __restrict__ b, const float* __restrict__ hin,
    float* __restrict__ out) {
    extern __shared__ float sm[];
    uint32_t* sWt = (uint32_t*)sm;            // [64][WPITCH] tf32, transposed
    float*    sA  = sm + 64*WPITCH;           // NSTG stages x [128][APITCH]
    const int tid  = threadIdx.x;
    const int lane = tid & 31;
    const int wid  = tid >> 5;
    const int g    = lane >> 2;
    const int tig  = lane & 3;
    const int wm   = wid & 3;
    const int wn   = wid >> 2;

    for (int idx = tid; idx < KTOT*Dd; idx += 256) {
        int k = idx >> 6, n = idx & 63;
        float v = (k < KS) ? W[(size_t)k*Dd + n] : Wroot[(size_t)(k-KS)*Dd + n];
        sWt[n*WPITCH + k] = f2tf32(v);
    }
    __syncthreads();

    const uint32_t sA_u32 = (uint32_t)__cvta_generic_to_shared(sA);

    for (int tile = blockIdx.x; tile < NTILES; tile += gridDim.x) {
        const int node0 = tile * TILE;

        auto issue = [&](int kc) {
            const int stage = kc & (NSTG - 1);
            #pragma unroll
            for (int u = 0; u < 4; u++) {
                int idx  = tid + u*256;
                int nd   = idx >> 3;
                int part = idx & 7;
                int n    = node0 + nd;
                int nc   = (n < Nn) ? n : (Nn - 1);
                const float* src = (kc < 16)
                    ? g_S + (size_t)nc*KS + kc*KC + part*4
                    : hin + (size_t)nc*Dd + (kc-16)*KC + part*4;
                cp16(sA_u32 + (uint32_t)(((stage*TILE + nd)*APITCH + part*4) * 4), src);
            }
            cp_commit();
        };

        float acc[2][4][4];
        #pragma unroll
        for (int mf = 0; mf < 2; mf++)
            #pragma unroll
            for (int nf = 0; nf < 4; nf++)
                { acc[mf][nf][0]=0.f; acc[mf][nf][1]=0.f; acc[mf][nf][2]=0.f; acc[mf][nf][3]=0.f; }

        issue(0); issue(1); issue(2);
        for (int kc = 0; kc < NCHK; kc++) {
            cp_wait<2>();
            __syncthreads();
            const float* aS = sA + (kc & (NSTG - 1))*TILE*APITCH;
            #pragma unroll
            for (int ks = 0; ks < KC/8; ks++) {
                const int kl = ks*8;
                const int kg = kc*KC + kl;
                #pragma unroll
                for (int mf = 0; mf < 2; mf++) {
                    const float* ap = aS + (wm*32 + mf*16)*APITCH + kl;
                    uint32_t a0 = f2tf32(ap[ g     *APITCH + tig    ]);
                    uint32_t a1 = f2tf32(ap[(g + 8)*APITCH + tig    ]);
                    uint32_t a2 = f2tf32(ap[ g     *APITCH + tig + 4]);
                    uint32_t a3 = f2tf32(ap[(g + 8)*APITCH + tig + 4]);
                    #pragma unroll
                    for (int nf = 0; nf < 4; nf++) {
                        const uint32_t* bp = sWt + (wn*32 + nf*8 + g)*WPITCH + kg + tig;
                        mma_tf32(acc[mf][nf], a0, a1, a2, a3, bp[0], bp[4]);
                    }
                }
            }
            __syncthreads();
            if (kc + 3 < NCHK) issue(kc + 3);
            else               cp_commit();
        }

        #pragma unroll
        for (int mf = 0; mf < 2; mf++) {
            #pragma unroll
            for (int nf = 0; nf < 4; nf++) {
                int col = wn*32 + nf*8 + tig*2;
                float2 bv = *(const float2*)(b + col);
                #pragma unroll
                for (int half = 0; half < 2; half++) {
                    int r = node0 + wm*32 + mf*16 + g + half*8;
                    if (r < Nn) {
                        float2 hv = *(const float2*)(hin + (size_t)r*Dd + col);
                        float2 o;
                        o.x = hv.x + fmaxf(acc[mf][nf][half*2 + 0] + bv.x, 0.f);
                        o.y = hv.y + fmaxf(acc[mf][nf][half*2 + 1] + bv.y, 0.f);
                        *(float2*)(out + (size_t)r*Dd + col) = o;
                    }
                }
            }
        }
    }
}

// ---------------------------------------------------------------------------
extern "C" void kernel_launch(void* const* d_in, const int* in_sizes, int n_in,
                              void* d_out, int out_size) {
    const int*   x     = (const int*)d_in[0];
    const int*   eidx  = (const int*)d_in[1];
    const int*   et    = (const int*)d_in[2];
    const int*   ntype = (const int*)d_in[3];
    const float* props = (const float*)d_in[4];
    const float* nemb  = (const float*)d_in[5];
    const float* temb  = (const float*)d_in[6];
    const float* pw1   = (const float*)d_in[7];
    const float* pb1   = (const float*)d_in[8];
    const float* pw2   = (const float*)d_in[9];
    const float* pb2   = (const float*)d_in[10];
    const float* W1    = (const float*)d_in[11];
    const float* Wr1   = (const float*)d_in[12];
    const float* b1    = (const float*)d_in[13];
    const float* W2    = (const float*)d_in[14];
    const float* Wr2   = (const float*)d_in[15];
    const float* b2    = (const float*)d_in[16];
    float* out = (float*)d_out;
    const int* src = eidx;
    const int* dst = eidx + Ee;

    void *pcnt, *pcur, *ph, *ph2;
    cudaGetSymbolAddress(&pcnt, g_cnt);
    cudaGetSymbolAddress(&pcur, g_cur);
    cudaGetSymbolAddress(&ph,   g_h);
    cudaGetSymbolAddress(&ph2,  g_h2);
    float* h  = (float*)ph;
    float* h2 = (float*)ph2;

    size_t smem = (size_t)(64*WPITCH + NSTG*TILE*APITCH) * sizeof(float);
    cudaFuncSetAttribute(transform_k, cudaFuncAttributeMaxDynamicSharedMemorySize, (int)smem);

    // ---- CSR build (graph structure; no g_S memset needed anymore) ----
    cudaMemsetAsync(pcnt, 0, sizeof(int)*NR);
    cudaMemsetAsync(pcur, 0, sizeof(int)*NR);
    count_k<<<(Ee+255)/256, 256>>>(dst, et);
    inv_k<<<(NR+255)/256, 256>>>();
    scan1_k<<<SCAN_BLKS, 256>>>();
    scan2_k<<<1, 256>>>();
    scan3_k<<<(NR+255)/256, 256>>>();
    fill_k<<<(Ee+255)/256, 256>>>(src, dst, et);
    mlp_k<<<1536, 256>>>(x, ntype, props, nemb, temb, pw1, pb1, pw2, pb2);

    // layer 1
    seg_sum_k<<<3200, 256>>>(h);
    transform_k<<<148, 256, smem>>>(W1, Wr1, b1, h, h2);

    // layer 2
    seg_sum_k<<<3200, 256>>>(h2);
    transform_k<<<148, 256, smem>>>(W2, Wr2, b2, h2, out);
}